// round 1
// baseline (speedup 1.0000x reference)
#include <cuda_runtime.h>

#define VOCAB  30522
#define HIDDEN 768
#define EMBED  512
#define BATCH  16
#define SEQ    512
#define WSUB   4
#define MROWS  (BATCH*SEQ)   // 8192

// ---- scratch (static __device__ — allocation-free per harness rules) ----
__device__ float g_pooled[(size_t)MROWS * HIDDEN];  // compacted pooled embeddings (~25 MB)
__device__ int   g_dest[MROWS];                     // word -> compacted slot (-1 if invalid)
__device__ int   g_lens[BATCH];                     // valid words per batch
__device__ float g_padout[EMBED];                   // leaky(pad_vec @ W + b)

// ---- packed fp32x2 helpers (Blackwell FFMA2 path, PTX-only) ----
__device__ __forceinline__ void fma2(unsigned long long &d, unsigned long long a, unsigned long long b) {
    asm("fma.rn.f32x2 %0, %1, %2, %0;" : "+l"(d) : "l"(a), "l"(b));
}
__device__ __forceinline__ unsigned long long pack2(float lo, float hi) {
    unsigned long long r;
    asm("mov.b64 %0, {%1, %2};" : "=l"(r) : "f"(lo), "f"(hi));
    return r;
}
__device__ __forceinline__ void unpack2(float &lo, float &hi, unsigned long long v) {
    asm("mov.b64 {%0, %1}, %2;" : "=f"(lo), "=f"(hi) : "l"(v));
}

// ============================================================
// Kernel 1: per-batch stable compaction scan. grid=16, block=512
// ============================================================
__global__ void scan_kernel(const int* __restrict__ words) {
    __shared__ int buf[SEQ];
    const int b = blockIdx.x;
    const int s = threadIdx.x;
    const int* wp = words + ((size_t)(b * SEQ + s)) * WSUB;
    int v = (wp[0] != 0) || (wp[1] != 0) || (wp[2] != 0) || (wp[3] != 0);
    buf[s] = v;
    __syncthreads();
    #pragma unroll
    for (int off = 1; off < SEQ; off <<= 1) {
        int t = (s >= off) ? buf[s - off] : 0;
        __syncthreads();
        buf[s] += t;
        __syncthreads();
    }
    int incl = buf[s];
    g_dest[b * SEQ + s] = v ? (incl - 1) : -1;
    if (s == SEQ - 1) g_lens[b] = incl;
}

// ============================================================
// Kernel 2: pad output row = leaky(embed[words[2047]] @ W + b)
// grid=512 (one per output col), block=32 (warp reduce)
// ============================================================
__global__ void padout_kernel(const int* __restrict__ words,
                              const float* __restrict__ et,
                              const float* __restrict__ Wf,
                              const float* __restrict__ bias) {
    const int j = blockIdx.x;
    const int lane = threadIdx.x;
    const int pad_id = words[(0 * SEQ + (SEQ - 1)) * WSUB + (WSUB - 1)];  // words[2047]
    const float* e = et + (size_t)pad_id * HIDDEN;
    float p = 0.f;
    #pragma unroll 4
    for (int k = lane; k < HIDDEN; k += 32)
        p = fmaf(e[k], Wf[(size_t)k * EMBED + j], p);
    #pragma unroll
    for (int o = 16; o > 0; o >>= 1)
        p += __shfl_down_sync(0xFFFFFFFFu, p, o);
    if (lane == 0) {
        float x = p + bias[j];
        g_padout[j] = (x >= 0.f) ? x : 0.1f * x;
    }
}

// ============================================================
// Kernel 3: gather + masked mean-pool + compacting scatter
// grid=8192 (one word per block), block=192 (768 floats / float4)
// ============================================================
__global__ void pool_kernel(const int* __restrict__ words,
                            const float* __restrict__ et) {
    const int idx = blockIdx.x;           // b*512 + s
    const int d = g_dest[idx];
    if (d < 0) return;                    // invalid word: dropped by compaction
    const int* wp = words + (size_t)idx * WSUB;
    const int i0 = wp[0], i1 = wp[1], i2 = wp[2], i3 = wp[3];
    const float cnt = (float)((i0 != 0) + (i1 != 0) + (i2 != 0) + (i3 != 0));
    const float inv = 1.0f / cnt;         // cnt >= 1 because d >= 0
    const int t = threadIdx.x << 2;       // float4 slot

    float sx = 0.f, sy = 0.f, sz = 0.f, sw = 0.f;
    if (i0 != 0) { float4 v = *(const float4*)(et + (size_t)i0 * HIDDEN + t); sx += v.x; sy += v.y; sz += v.z; sw += v.w; }
    if (i1 != 0) { float4 v = *(const float4*)(et + (size_t)i1 * HIDDEN + t); sx += v.x; sy += v.y; sz += v.z; sw += v.w; }
    if (i2 != 0) { float4 v = *(const float4*)(et + (size_t)i2 * HIDDEN + t); sx += v.x; sy += v.y; sz += v.z; sw += v.w; }
    if (i3 != 0) { float4 v = *(const float4*)(et + (size_t)i3 * HIDDEN + t); sx += v.x; sy += v.y; sz += v.z; sw += v.w; }

    const int row = (idx & ~(SEQ - 1)) + d;   // batch base + compacted slot
    float4 o = make_float4(sx * inv, sy * inv, sz * inv, sw * inv);
    *(float4*)(g_pooled + (size_t)row * HIDDEN + t) = o;
}

// ============================================================
// Kernel 4: [8192,768] @ [768,512] + bias + leaky + pad-tail epilogue
// 128x128 tile, BK=8, 256 threads, 8x8 microtile, packed f32x2 FMA
// grid=(4, 64)
// ============================================================
__global__ __launch_bounds__(256, 2)
void gemm_kernel(const float* __restrict__ Wf,
                 const float* __restrict__ bias,
                 float* __restrict__ out) {
    __shared__ float As[8][132];   // [k][m], padded to kill store conflicts (528B = 16B-aligned rows)
    __shared__ float Bs[8][128];   // [k][n]

    const int tid = threadIdx.x;
    const int bm0 = blockIdx.y * 128;    // block spans one quarter of a single batch
    const int bn0 = blockIdx.x * 128;

    const int arow = tid >> 1;           // A tile load: 128 rows x 8 cols
    const int acol = (tid & 1) << 2;
    const int brow = tid >> 5;           // B tile load: 8 rows x 128 cols
    const int bcol = (tid & 31) << 2;

    const int tx = tid & 15, ty = tid >> 4;
    const int rm = ty << 3, cn = tx << 3;

    const float* Ap = g_pooled + (size_t)(bm0 + arow) * HIDDEN + acol;
    const float* Bp = Wf + (size_t)brow * EMBED + bn0 + bcol;

    unsigned long long acc[8][4];        // 8 rows x 4 packed fp32-pairs (= 8 cols)
    #pragma unroll
    for (int i = 0; i < 8; i++)
        #pragma unroll
        for (int j = 0; j < 4; j++) acc[i][j] = 0ull;

    // prefetch first tile
    float4 av = *(const float4*)Ap;
    float4 bv = *(const float4*)Bp;

    for (int k0 = 0; k0 < HIDDEN; k0 += 8) {
        As[acol + 0][arow] = av.x;
        As[acol + 1][arow] = av.y;
        As[acol + 2][arow] = av.z;
        As[acol + 3][arow] = av.w;
        *(float4*)&Bs[brow][bcol] = bv;
        __syncthreads();

        if (k0 + 8 < HIDDEN) {           // prefetch next tile under compute
            av = *(const float4*)(Ap + k0 + 8);
            bv = *(const float4*)(Bp + (size_t)(k0 + 8) * EMBED);
        }

        #pragma unroll
        for (int k = 0; k < 8; k++) {
            float4 a0 = *(const float4*)&As[k][rm];
            float4 a1 = *(const float4*)&As[k][rm + 4];
            ulonglong2 b0 = *(const ulonglong2*)&Bs[k][cn];      // adjacent cols already paired
            ulonglong2 b1 = *(const ulonglong2*)&Bs[k][cn + 4];
            const unsigned long long bb0 = b0.x, bb1 = b0.y, bb2 = b1.x, bb3 = b1.y;
            float a[8] = {a0.x, a0.y, a0.z, a0.w, a1.x, a1.y, a1.z, a1.w};
            #pragma unroll
            for (int i = 0; i < 8; i++) {
                unsigned long long ad = pack2(a[i], a[i]);
                fma2(acc[i][0], ad, bb0);
                fma2(acc[i][1], ad, bb1);
                fma2(acc[i][2], ad, bb2);
                fma2(acc[i][3], ad, bb3);
            }
        }
        __syncthreads();
    }

    // ---- epilogue: bias + leaky for valid rows; pad row for tail ----
    const int bidx = bm0 >> 9;           // whole block is inside one batch (512/128 = 4)
    const int len = g_lens[bidx];
    const int s0 = (bm0 & (SEQ - 1)) + rm;

    float br[8], po[8];
    #pragma unroll
    for (int j = 0; j < 8; j++) {
        br[j] = bias[bn0 + cn + j];
        po[j] = g_padout[bn0 + cn + j];
    }

    #pragma unroll
    for (int i = 0; i < 8; i++) {
        float v[8];
        #pragma unroll
        for (int jj = 0; jj < 4; jj++) {
            float lo, hi;
            unpack2(lo, hi, acc[i][jj]);
            v[2 * jj] = lo; v[2 * jj + 1] = hi;
        }
        if (s0 + i < len) {
            #pragma unroll
            for (int j = 0; j < 8; j++) {
                float x = v[j] + br[j];
                v[j] = (x >= 0.f) ? x : 0.1f * x;
            }
        } else {
            #pragma unroll
            for (int j = 0; j < 8; j++) v[j] = po[j];
        }
        float* op = out + (size_t)(bm0 + rm + i) * EMBED + bn0 + cn;
        *(float4*)op       = make_float4(v[0], v[1], v[2], v[3]);
        *((float4*)op + 1) = make_float4(v[4], v[5], v[6], v[7]);
    }
}

// ============================================================
extern "C" void kernel_launch(void* const* d_in, const int* in_sizes, int n_in,
                              void* d_out, int out_size) {
    const int*   words = (const int*)  d_in[0];
    const float* et    = (const float*)d_in[1];
    const float* wf    = (const float*)d_in[2];
    const float* bf    = (const float*)d_in[3];
    float* out = (float*)d_out;

    scan_kernel<<<BATCH, SEQ>>>(words);
    padout_kernel<<<EMBED, 32>>>(words, et, wf, bf);
    pool_kernel<<<MROWS, HIDDEN / 4>>>(words, et);
    gemm_kernel<<<dim3(EMBED / 128, MROWS / 128), 256>>>(wf, bf, out);
}

// round 3
// speedup vs baseline: 3.8201x; 3.8201x over previous
#include <cuda_runtime.h>
#include <cuda_fp16.h>
#include <stdint.h>

#define VOCAB  30522
#define HIDDEN 768
#define EMBED  512
#define BATCH  16
#define SEQ    512
#define WSUB   4
#define MROWS  (BATCH*SEQ)     // 8192

#define BK     64              // k per stage (64 halves = 128B rows)
#define NCH    (HIDDEN/BK)     // 12 k-chunks
#define MT     128
#define NT     128
#define STAGES 3
#define A_ST   (MT*128)        // 16 KB
#define B_ST   (NT*128)        // 16 KB
#define STG_B  (A_ST + B_ST)   // 32 KB
#define SMEM_TOTAL (STAGES*STG_B + 128)

// ---- scratch (__device__ globals: allocation-free) ----
__device__ __align__(256) __half g_A [(size_t)MROWS*HIDDEN];   // pooled, compacted, fp16
__device__ __align__(256) __half g_Wt[(size_t)EMBED*HIDDEN];   // W^T  [N=512][K=768] fp16
__device__ int   g_dest[MROWS];
__device__ int   g_lens[BATCH];
__device__ float g_padout[EMBED];

// ================= PTX helpers =================
__device__ __forceinline__ uint32_t smem_u32(const void* p) {
    uint32_t a;
    asm("{ .reg .u64 t; cvta.to.shared.u64 t, %1; cvt.u32.u64 %0, t; }" : "=r"(a) : "l"(p));
    return a;
}
#define CP16(dst, src)  asm volatile("cp.async.cg.shared.global [%0], [%1], 16;" :: "r"(dst), "l"(src))
#define CP_COMMIT()     asm volatile("cp.async.commit_group;" ::: "memory")
#define CP_WAIT2()      asm volatile("cp.async.wait_group 2;" ::: "memory")

__device__ __forceinline__ void ldsm_x4(uint32_t* r, uint32_t addr) {
    asm volatile("ldmatrix.sync.aligned.m8n8.x4.shared.b16 {%0,%1,%2,%3}, [%4];"
        : "=r"(r[0]), "=r"(r[1]), "=r"(r[2]), "=r"(r[3]) : "r"(addr));
}
__device__ __forceinline__ void mma16816(float* d, const uint32_t* a, uint32_t b0, uint32_t b1) {
    asm volatile("mma.sync.aligned.m16n8k16.row.col.f32.f16.f16.f32 "
        "{%0,%1,%2,%3}, {%4,%5,%6,%7}, {%8,%9}, {%0,%1,%2,%3};"
        : "+f"(d[0]), "+f"(d[1]), "+f"(d[2]), "+f"(d[3])
        : "r"(a[0]), "r"(a[1]), "r"(a[2]), "r"(a[3]), "r"(b0), "r"(b1));
}

// ============================================================
// Kernel 1: per-batch stable compaction scan. grid=16, block=512
// ============================================================
__global__ void scan_kernel(const int* __restrict__ words) {
    __shared__ int buf[SEQ];
    const int b = blockIdx.x, s = threadIdx.x;
    const int* wp = words + ((size_t)(b * SEQ + s)) * WSUB;
    int v = (wp[0] != 0) || (wp[1] != 0) || (wp[2] != 0) || (wp[3] != 0);
    buf[s] = v;
    __syncthreads();
    #pragma unroll
    for (int off = 1; off < SEQ; off <<= 1) {
        int t = (s >= off) ? buf[s - off] : 0;
        __syncthreads();
        buf[s] += t;
        __syncthreads();
    }
    int incl = buf[s];
    g_dest[b * SEQ + s] = v ? (incl - 1) : -1;
    if (s == SEQ - 1) g_lens[b] = incl;
}

// ============================================================
// Kernel 2: pad row = leaky(embed[words[2047]] @ W + b)  (exact fp32)
// ============================================================
__global__ void padout_kernel(const int* __restrict__ words,
                              const float* __restrict__ et,
                              const float* __restrict__ Wf,
                              const float* __restrict__ bias) {
    const int j = blockIdx.x, lane = threadIdx.x;
    const int pad_id = words[(SEQ - 1) * WSUB + (WSUB - 1)];
    const float* e = et + (size_t)pad_id * HIDDEN;
    float p = 0.f;
    #pragma unroll 4
    for (int k = lane; k < HIDDEN; k += 32)
        p = fmaf(e[k], Wf[(size_t)k * EMBED + j], p);
    #pragma unroll
    for (int o = 16; o > 0; o >>= 1) p += __shfl_down_sync(0xFFFFFFFFu, p, o);
    if (lane == 0) {
        float x = p + bias[j];
        g_padout[j] = (x >= 0.f) ? x : 0.1f * x;
    }
}

// ============================================================
// Kernel 3: transpose W [768][512] f32 -> g_Wt [512][768] f16
// grid=(24,16), block=(32,8)
// ============================================================
__global__ void wtrans_kernel(const float* __restrict__ Wf) {
    __shared__ float sh[32][33];
    const int ks = blockIdx.x * 32, ns = blockIdx.y * 32;
    const int tx = threadIdx.x, ty = threadIdx.y;
    #pragma unroll
    for (int i = 0; i < 4; i++)
        sh[ty + 8 * i][tx] = Wf[(size_t)(ks + ty + 8 * i) * EMBED + ns + tx];
    __syncthreads();
    #pragma unroll
    for (int i = 0; i < 4; i++) {
        const int n = ns + ty + 8 * i, k = ks + tx;
        g_Wt[(size_t)n * HIDDEN + k] = __float2half(sh[tx][ty + 8 * i]);
    }
}

// ============================================================
// Kernel 4: gather + masked mean-pool + compaction -> fp16
// grid=8192, block=192
// ============================================================
__global__ void pool_kernel(const int* __restrict__ words,
                            const float* __restrict__ et) {
    const int idx = blockIdx.x;
    const int d = g_dest[idx];
    if (d < 0) return;
    const int* wp = words + (size_t)idx * WSUB;
    const int i0 = wp[0], i1 = wp[1], i2 = wp[2], i3 = wp[3];
    const float cnt = (float)((i0 != 0) + (i1 != 0) + (i2 != 0) + (i3 != 0));
    const float inv = 1.0f / cnt;
    const int t = threadIdx.x << 2;

    float s[4] = {0.f, 0.f, 0.f, 0.f};
    if (i0 != 0) { float4 v = *(const float4*)(et + (size_t)i0 * HIDDEN + t); s[0] += v.x; s[1] += v.y; s[2] += v.z; s[3] += v.w; }
    if (i1 != 0) { float4 v = *(const float4*)(et + (size_t)i1 * HIDDEN + t); s[0] += v.x; s[1] += v.y; s[2] += v.z; s[3] += v.w; }
    if (i2 != 0) { float4 v = *(const float4*)(et + (size_t)i2 * HIDDEN + t); s[0] += v.x; s[1] += v.y; s[2] += v.z; s[3] += v.w; }
    if (i3 != 0) { float4 v = *(const float4*)(et + (size_t)i3 * HIDDEN + t); s[0] += v.x; s[1] += v.y; s[2] += v.z; s[3] += v.w; }

    const int row = (idx & ~(SEQ - 1)) + d;
    __half2 p0; p0.x = __float2half(s[0] * inv); p0.y = __float2half(s[1] * inv);
    __half2 p1; p1.x = __float2half(s[2] * inv); p1.y = __float2half(s[3] * inv);
    __half2* dst = (__half2*)(g_A + (size_t)row * HIDDEN + t);
    dst[0] = p0;
    dst[1] = p1;
}

// ============================================================
// Kernel 5: fp16 HMMA GEMM [8192x512, K=768] + fused epilogue
// CTA 128x128, 8 warps (2x4) of 64x32, BK=64, 3-stage cp.async
// grid=(4,64), block=256, 2 CTAs/SM
// ============================================================
__device__ __forceinline__ void load_stage(int j, int tid, uint32_t data0,
                                           int bm0, int bn0) {
    const int s = j % STAGES;
    const int kk = j * BK;
    const uint32_t abase = data0 + s * STG_B;
    const uint32_t bbase = abase + A_ST;
    #pragma unroll
    for (int it = 0; it < 4; it++) {
        int c = tid + it * 256;
        int r = c >> 3, c16 = c & 7;
        const void* src = g_A + (size_t)(bm0 + r) * HIDDEN + kk + c16 * 8;
        uint32_t dst = abase + (uint32_t)(r * 128) + (((uint32_t)c16 * 16) ^ ((uint32_t)(r & 7) << 4));
        CP16(dst, src);
    }
    #pragma unroll
    for (int it = 0; it < 4; it++) {
        int c = tid + it * 256;
        int r = c >> 3, c16 = c & 7;
        const void* src = g_Wt + (size_t)(bn0 + r) * HIDDEN + kk + c16 * 8;
        uint32_t dst = bbase + (uint32_t)(r * 128) + (((uint32_t)c16 * 16) ^ ((uint32_t)(r & 7) << 4));
        CP16(dst, src);
    }
}

__global__ __launch_bounds__(256, 2)
void gemm_hmma_kernel(const float* __restrict__ bias, float* __restrict__ out) {
    extern __shared__ char smem[];
    const uint32_t data0 = (smem_u32(smem) + 127u) & ~127u;
    const int tid = threadIdx.x, lane = tid & 31, wid = tid >> 5;
    const int wm = wid & 1, wn = wid >> 1;            // 2 x 4 warp grid
    const int bm0 = blockIdx.y * MT, bn0 = blockIdx.x * NT;

    // per-thread ldmatrix row bases (within warp tile)
    const int a_moff = (lane & 7) + ((lane >> 3) & 1) * 8;  // A: m-low/m-high pairs
    const int a_k8   = lane >> 4;
    const int b_noff = (lane & 7) + (lane >> 4) * 8;        // B: n-low/n-high pairs
    const int b_k8   = (lane >> 3) & 1;
    const uint32_t a_row = (uint32_t)((wm * 64 + a_moff) * 128);
    const uint32_t b_row = (uint32_t)(A_ST + (wn * 32 + b_noff) * 128);
    uint32_t akx[4], bkx[4];
    #pragma unroll
    for (int ks = 0; ks < 4; ks++) {
        akx[ks] = ((uint32_t)((ks * 2 + a_k8) * 16)) ^ ((uint32_t)(a_moff & 7) << 4);
        bkx[ks] = ((uint32_t)((ks * 2 + b_k8) * 16)) ^ ((uint32_t)(b_noff & 7) << 4);
    }

    float acc[4][4][4];
    #pragma unroll
    for (int i = 0; i < 4; i++)
        #pragma unroll
        for (int j = 0; j < 4; j++)
            #pragma unroll
            for (int q = 0; q < 4; q++) acc[i][j][q] = 0.f;

    load_stage(0, tid, data0, bm0, bn0); CP_COMMIT();
    load_stage(1, tid, data0, bm0, bn0); CP_COMMIT();

    for (int i = 0; i < NCH; i++) {
        if (i + 2 < NCH) load_stage(i + 2, tid, data0, bm0, bn0);
        CP_COMMIT();
        CP_WAIT2();
        __syncthreads();

        const uint32_t sa = data0 + (i % STAGES) * STG_B;
        #pragma unroll
        for (int ks = 0; ks < 4; ks++) {
            uint32_t a[4][4], b[2][4];
            #pragma unroll
            for (int mt = 0; mt < 4; mt++)
                ldsm_x4(a[mt], sa + a_row + (uint32_t)(mt * 2048) + akx[ks]);
            #pragma unroll
            for (int np = 0; np < 2; np++)
                ldsm_x4(b[np], sa + b_row + (uint32_t)(np * 2048) + bkx[ks]);
            #pragma unroll
            for (int mt = 0; mt < 4; mt++) {
                #pragma unroll
                for (int np = 0; np < 2; np++) {
                    mma16816(acc[mt][np * 2 + 0], a[mt], b[np][0], b[np][1]);
                    mma16816(acc[mt][np * 2 + 1], a[mt], b[np][2], b[np][3]);
                }
            }
        }
        __syncthreads();
    }

    // ---- epilogue: bias + leaky on valid rows, pad row on tail ----
    const int coln = bn0 + wn * 32 + (lane & 3) * 2;
    float2 bj[4], pj[4];
    #pragma unroll
    for (int nt = 0; nt < 4; nt++) {
        const int c = coln + nt * 8;
        bj[nt] = make_float2(__ldg(bias + c), __ldg(bias + c + 1));
        pj[nt] = make_float2(g_padout[c], g_padout[c + 1]);
    }
    #pragma unroll
    for (int mt = 0; mt < 4; mt++) {
        const int r0 = bm0 + wm * 64 + mt * 16 + (lane >> 2);
        const int len = g_lens[r0 >> 9];
        const bool v0 = (r0 & (SEQ - 1)) < len;
        const bool v1 = ((r0 + 8) & (SEQ - 1)) < len;
        #pragma unroll
        for (int nt = 0; nt < 4; nt++) {
            const int c = coln + nt * 8;
            float2 o0, o1;
            if (v0) {
                float x = acc[mt][nt][0] + bj[nt].x, y = acc[mt][nt][1] + bj[nt].y;
                o0 = make_float2(fmaxf(x, 0.1f * x), fmaxf(y, 0.1f * y));
            } else o0 = pj[nt];
            if (v1) {
                float x = acc[mt][nt][2] + bj[nt].x, y = acc[mt][nt][3] + bj[nt].y;
                o1 = make_float2(fmaxf(x, 0.1f * x), fmaxf(y, 0.1f * y));
            } else o1 = pj[nt];
            *(float2*)(out + (size_t)r0 * EMBED + c)       = o0;
            *(float2*)(out + (size_t)(r0 + 8) * EMBED + c) = o1;
        }
    }
}

// ============================================================
extern "C" void kernel_launch(void* const* d_in, const int* in_sizes, int n_in,
                              void* d_out, int out_size) {
    const int*   words = (const int*)  d_in[0];
    const float* et    = (const float*)d_in[1];
    const float* wf    = (const float*)d_in[2];
    const float* bf    = (const float*)d_in[3];
    float* out = (float*)d_out;

    cudaFuncSetAttribute(gemm_hmma_kernel,
                         cudaFuncAttributeMaxDynamicSharedMemorySize, SMEM_TOTAL);

    scan_kernel<<<BATCH, SEQ>>>(words);
    padout_kernel<<<EMBED, 32>>>(words, et, wf, bf);
    wtrans_kernel<<<dim3(HIDDEN / 32, EMBED / 32), dim3(32, 8)>>>(wf);
    pool_kernel<<<MROWS, HIDDEN / 4>>>(words, et);
    gemm_hmma_kernel<<<dim3(EMBED / NT, MROWS / MT), 256, SMEM_TOTAL>>>(bf, out);
}